// round 10
// baseline (speedup 1.0000x reference)
#include <cuda_runtime.h>
#include <cstdint>

#define DIM 128
#define NMAX 50000
#define EPW 8

// Scratch (no cudaMalloc allowed)
__device__ float g_M[(size_t)NMAX * DIM];    // msg_lin(X)
__device__ float g_agg[(size_t)NMAX * DIM];  // (1+eps)*X + scatter-add
__device__ float g_Wt_msg[DIM * DIM];        // msg_w transposed (FFMA fallback)
__device__ float g_Wt_lin[DIM * DIM];        // lin_w transposed (FFMA fallback)
__device__ int   g_is64;
__device__ int   g_fallback;

// ---------------------------------------------------------------------------
__device__ __forceinline__ uint32_t f2tf32(float x) {
    uint32_t r;
    asm("cvt.rna.tf32.f32 %0, %1;" : "=r"(r) : "f"(x));
    return r;
}
__device__ __forceinline__ void tf32_split(float x, uint32_t& h, uint32_t& l) {
    h = f2tf32(x);
    l = f2tf32(x - __uint_as_float(h));
}
// m16n8k8 tf32 warp MMA (baseline PTX, works on plain sm_103 target)
__device__ __forceinline__ void mma8(float* c, const uint32_t* a, const uint32_t* b) {
    asm volatile(
        "mma.sync.aligned.m16n8k8.row.col.f32.tf32.tf32.f32 "
        "{%0,%1,%2,%3}, {%4,%5,%6,%7}, {%8,%9}, {%0,%1,%2,%3};"
        : "+f"(c[0]), "+f"(c[1]), "+f"(c[2]), "+f"(c[3])
        : "r"(a[0]), "r"(a[1]), "r"(a[2]), "r"(a[3]), "r"(b[0]), "r"(b[1]));
}

// ---------------------------------------------------------------------------
// Detect edge_index dtype; reset fallback flag (deterministic per launch).
// ---------------------------------------------------------------------------
__global__ void detect_kernel(const unsigned* __restrict__ e) {
    int is64 = 1;
    for (int i = 1; i < 256; i += 2) {
        if (e[i] != 0u) { is64 = 0; break; }
    }
    g_is64 = is64;
    g_fallback = 0;
}

// ---------------------------------------------------------------------------
// One-time weight transposes for the FFMA fallback path.
// ---------------------------------------------------------------------------
__global__ void transpose_w_kernel(const float* __restrict__ W_msg,
                                   const float* __restrict__ W_lin)
{
    __shared__ float tile[32][33];
    const float* W  = blockIdx.z ? W_lin : W_msg;
    float*       Wt = blockIdx.z ? g_Wt_lin : g_Wt_msg;
    int tx = threadIdx.x, ty = threadIdx.y;
    int x = blockIdx.x * 32 + tx, y = blockIdx.y * 32 + ty;
    #pragma unroll
    for (int j = 0; j < 32; j += 8)
        tile[ty + j][tx] = W[(y + j) * DIM + x];
    __syncthreads();
    int x2 = blockIdx.y * 32 + tx, y2 = blockIdx.x * 32 + ty;
    #pragma unroll
    for (int j = 0; j < 32; j += 8)
        Wt[(y2 + j) * DIM + x2] = tile[tx][ty + j];
}

// ---------------------------------------------------------------------------
// 3xTF32 warp-MMA GEMM: C[n,g] = relu?( sum_f A[n,f]*W[g,f] + bias[g] )
// CTA: 256 threads, tile 128 rows x 128 cols. Warp grid 2(m) x 4(n); each
// warp owns 64x32 = 4x4 m16n8k8 tiles. X/W staged fp32 in smem (stride 132
// -> fragment LDS conflict-free: bank = 4*row+col, all distinct in a warp).
// Hi/lo tf32 split done in registers; 3 MMAs per tile (hh, hl, lh).
// W is used directly as the col-major B operand (B[n][k] = W[g][f]).
// ---------------------------------------------------------------------------
template <bool FUSE_AGG, bool RELU>
__global__ __launch_bounds__(256)
void gemm_mma(const float* __restrict__ A, const float* __restrict__ W,
              const float* __restrict__ bias, float* __restrict__ C,
              float* __restrict__ agg, const float* __restrict__ eps_ptr,
              int N)
{
    extern __shared__ float sm[];
    float* Xs = sm;             // [128][132]
    float* Ws = sm + 128 * 132; // [128][132]

    const int tid = threadIdx.x, lane = tid & 31, wid = tid >> 5;
    const int row0 = blockIdx.x * 128;

    // Stage X tile (clamped rows) and full W, both coalesced.
    #pragma unroll 4
    for (int i = tid; i < 128 * 32; i += 256) {
        int r = i >> 5, c4 = (i & 31) * 4;
        int gr = row0 + r; if (gr >= N) gr = N - 1;
        *(float4*)&Xs[r * 132 + c4] = *(const float4*)(A + (size_t)gr * DIM + c4);
        *(float4*)&Ws[r * 132 + c4] = *(const float4*)(W + (size_t)r * DIM + c4);
    }
    __syncthreads();

    const int wm = (wid & 1) * 64;      // warp row base within tile
    const int wn = (wid >> 1) * 32;     // warp col base within tile
    const int gid = lane >> 2;          // 0..7
    const int qid = lane & 3;           // 0..3

    float acc[4][4][4];
    #pragma unroll
    for (int mt = 0; mt < 4; mt++)
        #pragma unroll
        for (int nt = 0; nt < 4; nt++)
            #pragma unroll
            for (int j = 0; j < 4; j++) acc[mt][nt][j] = 0.f;

    #pragma unroll 1
    for (int kt = 0; kt < 16; kt++) {
        const int k0 = kt * 8;
        // B fragments: b0 = W[n=gid][k=qid], b1 = W[n=gid][k=qid+4]
        uint32_t bh[4][2], bl[4][2];
        #pragma unroll
        for (int nt = 0; nt < 4; nt++) {
            const float* wr = &Ws[(wn + nt * 8 + gid) * 132 + k0 + qid];
            tf32_split(wr[0], bh[nt][0], bl[nt][0]);
            tf32_split(wr[4], bh[nt][1], bl[nt][1]);
        }
        #pragma unroll
        for (int mt = 0; mt < 4; mt++) {
            const int r = wm + mt * 16 + gid;
            // A fragments: a0=(r,q) a1=(r+8,q) a2=(r,q+4) a3=(r+8,q+4)
            uint32_t ah[4], al[4];
            tf32_split(Xs[r * 132 + k0 + qid],           ah[0], al[0]);
            tf32_split(Xs[(r + 8) * 132 + k0 + qid],     ah[1], al[1]);
            tf32_split(Xs[r * 132 + k0 + qid + 4],       ah[2], al[2]);
            tf32_split(Xs[(r + 8) * 132 + k0 + qid + 4], ah[3], al[3]);
            #pragma unroll
            for (int nt = 0; nt < 4; nt++) {
                mma8(acc[mt][nt], ah, bh[nt]);
                mma8(acc[mt][nt], ah, bl[nt]);
                mma8(acc[mt][nt], al, bh[nt]);
            }
        }
    }

    // Epilogue: c0=(r,2q) c1=(r,2q+1) c2=(r+8,2q) c3=(r+8,2q+1)
    #pragma unroll
    for (int mt = 0; mt < 4; mt++) {
        int r0 = row0 + wm + mt * 16 + gid;
        int r1 = r0 + 8;
        #pragma unroll
        for (int nt = 0; nt < 4; nt++) {
            int c = wn + nt * 8 + 2 * qid;
            float b0 = __ldg(&bias[c]), b1 = __ldg(&bias[c + 1]);
            float v0 = acc[mt][nt][0] + b0, v1 = acc[mt][nt][1] + b1;
            float v2 = acc[mt][nt][2] + b0, v3 = acc[mt][nt][3] + b1;
            if (RELU) {
                v0 = fmaxf(v0, 0.f); v1 = fmaxf(v1, 0.f);
                v2 = fmaxf(v2, 0.f); v3 = fmaxf(v3, 0.f);
            }
            if (r0 < N) *(float2*)(C + (size_t)r0 * DIM + c) = make_float2(v0, v1);
            if (r1 < N) *(float2*)(C + (size_t)r1 * DIM + c) = make_float2(v2, v3);
        }
    }

    if (FUSE_AGG) {
        float s = 1.0f + *eps_ptr;
        #pragma unroll 2
        for (int i = tid; i < 128 * 32; i += 256) {
            int r = i >> 5, c4 = (i & 31) * 4;
            int row = row0 + r;
            if (row < N) {
                float4 v = *(float4*)&Xs[r * 132 + c4];
                v.x *= s; v.y *= s; v.z *= s; v.w *= s;
                *(float4*)(agg + (size_t)row * DIM + c4) = v;
            }
        }
    }
}

// ---------------------------------------------------------------------------
// Verify g_M (phase-1 output) on 256 rows x 16 sampled cols vs FFMA ref.
// Any mismatch -> g_fallback=1 -> FFMA kernels recompute everything.
// ---------------------------------------------------------------------------
__global__ void verify_kernel(const float* __restrict__ X,
                              const float* __restrict__ Wm,
                              const float* __restrict__ bm, int N)
{
    int t = threadIdx.x;
    int r = t & 127;
    int half = t >> 7;
    int row = (blockIdx.x == 0) ? r : (N - 128 + r);
    const float* xr = X + (size_t)row * DIM;
    bool bad = false;
    #pragma unroll 1
    for (int j = 0; j < 8; j++) {
        int c = half * 64 + j * 8 + (r & 7);
        const float* wr = Wm + c * DIM;
        float a0 = 0.f, a1 = 0.f, a2 = 0.f, a3 = 0.f;
        for (int f = 0; f < 128; f += 4) {
            a0 += xr[f] * wr[f];         a1 += xr[f + 1] * wr[f + 1];
            a2 += xr[f + 2] * wr[f + 2]; a3 += xr[f + 3] * wr[f + 3];
        }
        float ref = bm[c] + ((a0 + a1) + (a2 + a3));
        float got = g_M[(size_t)row * DIM + c];
        if (!(fabsf(got - ref) <= 1e-3f * (fabsf(ref) + 1.0f))) bad = true;
    }
    if (bad) g_fallback = 1;
}

// ---------------------------------------------------------------------------
// FFMA fallback GEMM (no-op unless g_fallback==1).
// ---------------------------------------------------------------------------
template <bool FUSE_AGG, bool RELU>
__global__ __launch_bounds__(128)
void gemm_ffma(const float* __restrict__ A, const float* __restrict__ Wt_g,
               const float* __restrict__ bias, float* __restrict__ C,
               float* __restrict__ agg, const float* __restrict__ eps_ptr,
               int N, const int* __restrict__ flag)
{
    if (*flag == 0) return;
    extern __shared__ float smem[];
    float* Wt = smem;                 // [128][132]
    float* Xs = smem + 128 * 132;     // [64][128]
    const int tid = threadIdx.x;
    const int row0 = blockIdx.x * 64;

    #pragma unroll 8
    for (int i = tid; i < 128 * 32; i += 128) {
        int f = i >> 5, g4 = i & 31;
        *(float4*)(Wt + f * 132 + g4 * 4) = *(const float4*)(Wt_g + f * DIM + g4 * 4);
    }
    #pragma unroll 4
    for (int idx = tid; idx < 64 * 32; idx += 128) {
        int r = idx >> 5, c4 = idx & 31;
        float4 v = make_float4(0.f, 0.f, 0.f, 0.f);
        if (row0 + r < N)
            v = *(const float4*)(A + (size_t)(row0 + r) * DIM + c4 * 4);
        *(float4*)(Xs + r * DIM + c4 * 4) = v;
    }
    __syncthreads();

    const int warp = tid >> 5, lane = tid & 31;
    const int wrow = warp * 16 + (lane >> 4) * 8;
    const int c0   = (lane & 15) * 8;
    float acc[8][8];
    #pragma unroll
    for (int i = 0; i < 8; i++)
        #pragma unroll
        for (int j = 0; j < 8; j++) acc[i][j] = 0.f;

    #pragma unroll 2
    for (int k = 0; k < 128; k += 4) {
        float4 xv[8];
        #pragma unroll
        for (int i = 0; i < 8; i++)
            xv[i] = *(float4*)&Xs[(wrow + i) * DIM + k];
        #pragma unroll
        for (int kk = 0; kk < 4; kk++) {
            float4 wa = *(float4*)&Wt[(k + kk) * 132 + c0];
            float4 wb = *(float4*)&Wt[(k + kk) * 132 + c0 + 4];
            #pragma unroll
            for (int i = 0; i < 8; i++) {
                float xs = (&xv[i].x)[kk];
                acc[i][0] += xs * wa.x; acc[i][1] += xs * wa.y;
                acc[i][2] += xs * wa.z; acc[i][3] += xs * wa.w;
                acc[i][4] += xs * wb.x; acc[i][5] += xs * wb.y;
                acc[i][6] += xs * wb.z; acc[i][7] += xs * wb.w;
            }
        }
    }
    float bl[8];
    #pragma unroll
    for (int j = 0; j < 8; j++) bl[j] = bias[c0 + j];
    #pragma unroll
    for (int i = 0; i < 8; i++) {
        int r = row0 + wrow + i;
        if (r < N) {
            float4 o0, o1;
            o0.x = acc[i][0] + bl[0]; o0.y = acc[i][1] + bl[1];
            o0.z = acc[i][2] + bl[2]; o0.w = acc[i][3] + bl[3];
            o1.x = acc[i][4] + bl[4]; o1.y = acc[i][5] + bl[5];
            o1.z = acc[i][6] + bl[6]; o1.w = acc[i][7] + bl[7];
            if (RELU) {
                o0.x = fmaxf(o0.x, 0.f); o0.y = fmaxf(o0.y, 0.f);
                o0.z = fmaxf(o0.z, 0.f); o0.w = fmaxf(o0.w, 0.f);
                o1.x = fmaxf(o1.x, 0.f); o1.y = fmaxf(o1.y, 0.f);
                o1.z = fmaxf(o1.z, 0.f); o1.w = fmaxf(o1.w, 0.f);
            }
            *(float4*)(C + (size_t)r * DIM + c0)     = o0;
            *(float4*)(C + (size_t)r * DIM + c0 + 4) = o1;
        }
    }
    if (FUSE_AGG) {
        float s = 1.0f + *eps_ptr;
        #pragma unroll 4
        for (int idx = tid; idx < 64 * 32; idx += 128) {
            int r = idx >> 5, c4 = idx & 31;
            if (row0 + r < N) {
                float4 v = *(float4*)(Xs + r * DIM + c4 * 4);
                v.x *= s; v.y *= s; v.z *= s; v.w *= s;
                *(float4*)(agg + (size_t)(row0 + r) * DIM + c4 * 4) = v;
            }
        }
    }
}

// ---------------------------------------------------------------------------
// Scatter: EPW=8 edges per warp, batched gathers (MLP=8), RED.128 updates.
// ---------------------------------------------------------------------------
__global__ __launch_bounds__(256)
void scatter_kernel(const void* __restrict__ eidx, int E)
{
    const int lane = threadIdx.x & 31;
    const int warp = blockIdx.x * (blockDim.x >> 5) + (threadIdx.x >> 5);
    const int e0 = warp * EPW;
    if (e0 >= E) return;

    int src[EPW], dst[EPW];
    if (g_is64) {
        const long long* p = (const long long*)eidx;
        #pragma unroll
        for (int j = 0; j < EPW; j++) {
            int e = e0 + j;
            if (e < E) { src[j] = (int)p[e]; dst[j] = (int)p[(size_t)E + e]; }
            else       { src[j] = -1;        dst[j] = 0; }
        }
    } else {
        const int* p = (const int*)eidx;
        #pragma unroll
        for (int j = 0; j < EPW; j++) {
            int e = e0 + j;
            if (e < E) { src[j] = p[e]; dst[j] = p[E + e]; }
            else       { src[j] = -1;   dst[j] = 0; }
        }
    }

    float4 m[EPW];
    #pragma unroll
    for (int j = 0; j < EPW; j++)
        m[j] = *(const float4*)(g_M + (size_t)dst[j] * DIM + lane * 4);

    #pragma unroll
    for (int j = 0; j < EPW; j++) {
        if (src[j] >= 0) {
            float* a = g_agg + (size_t)src[j] * DIM + lane * 4;
            asm volatile("red.global.add.v4.f32 [%0], {%1, %2, %3, %4};"
                         :: "l"(a), "f"(m[j].x), "f"(m[j].y),
                            "f"(m[j].z), "f"(m[j].w)
                         : "memory");
        }
    }
}

// ---------------------------------------------------------------------------
extern "C" void kernel_launch(void* const* d_in, const int* in_sizes, int n_in,
                              void* d_out, int out_size)
{
    const float* X     = (const float*)d_in[0];
    const void*  eidx  = d_in[1];
    const float* eps   = (const float*)d_in[2];
    const float* msg_w = (const float*)d_in[3];
    const float* msg_b = (const float*)d_in[4];
    const float* lin_w = (const float*)d_in[5];
    const float* lin_b = (const float*)d_in[6];
    float* out = (float*)d_out;

    int N = in_sizes[0] / DIM;
    int E = in_sizes[1] / 2;

    float *Mptr, *aggptr, *WtMsg, *WtLin;
    int* flagptr;
    cudaGetSymbolAddress((void**)&Mptr, g_M);
    cudaGetSymbolAddress((void**)&aggptr, g_agg);
    cudaGetSymbolAddress((void**)&WtMsg, g_Wt_msg);
    cudaGetSymbolAddress((void**)&WtLin, g_Wt_lin);
    cudaGetSymbolAddress((void**)&flagptr, g_fallback);

    const int smemM = 2 * 128 * 132 * (int)sizeof(float);   // 135168
    const int smemF = (128 * 132 + 64 * 128) * (int)sizeof(float);
    cudaFuncSetAttribute(gemm_mma<true, false>,
                         cudaFuncAttributeMaxDynamicSharedMemorySize, smemM);
    cudaFuncSetAttribute(gemm_mma<false, true>,
                         cudaFuncAttributeMaxDynamicSharedMemorySize, smemM);
    cudaFuncSetAttribute(gemm_ffma<true, false>,
                         cudaFuncAttributeMaxDynamicSharedMemorySize, smemF);
    cudaFuncSetAttribute(gemm_ffma<false, true>,
                         cudaFuncAttributeMaxDynamicSharedMemorySize, smemF);

    transpose_w_kernel<<<dim3(4, 4, 2), dim3(32, 8)>>>(msg_w, lin_w);
    detect_kernel<<<1, 1>>>((const unsigned*)eidx);

    int gmm = (N + 127) / 128;
    int gff = (N + 63) / 64;

    // Phase 1: M = X @ msg_w^T + msg_b ; agg = (1+eps)*X   (3xTF32 warp-MMA)
    gemm_mma<true, false><<<gmm, 256, smemM>>>(X, msg_w, msg_b, Mptr,
                                               aggptr, eps, N);
    // Verify phase-1 output; sets g_fallback on mismatch.
    verify_kernel<<<2, 256>>>(X, msg_w, msg_b, N);
    // Conditional FFMA recompute (no-op when flag==0).
    gemm_ffma<true, false><<<gff, 128, smemF>>>(X, WtMsg, msg_b, Mptr,
                                                aggptr, eps, N, flagptr);
    // Phase 2: agg[src] += M[dst]
    int warps_needed = (E + EPW - 1) / EPW;
    int sblocks = (warps_needed + 7) / 8;
    scatter_kernel<<<sblocks, 256>>>(eidx, E);
    // Phase 3: out = relu(agg @ lin_w^T + lin_b)
    gemm_mma<false, true><<<gmm, 256, smemM>>>(aggptr, lin_w, lin_b, out,
                                               nullptr, nullptr, N);
    gemm_ffma<false, true><<<gff, 128, smemF>>>(aggptr, WtLin, lin_b, out,
                                                nullptr, nullptr, N, flagptr);
}